// round 13
// baseline (speedup 1.0000x reference)
#include <cuda_runtime.h>
#include <cuda_fp16.h>

#define DMODEL 1024
#define HEADS  16
#define DKH    64
#define BATCH  2
#define SEQ    2048
#define MR     (BATCH*SEQ)   // 4096 rows

// --------------------------- device scratch (no allocs) ---------------------
__device__ __half g_qh[MR*DMODEL];   // half copies of inputs
__device__ __half g_kh[MR*DMODEL];
__device__ __half g_vh[MR*DMODEL];
__device__ __half g_wqh[DMODEL*DMODEL];
__device__ __half g_wkh[DMODEL*DMODEL];
__device__ __half g_wvh[DMODEL*DMODEL];
__device__ __half g_woh[DMODEL*DMODEL];
__device__ __half g_qp[MR*DMODEL];   // projected, head-split [B,H,S,DKH], q scaled by log2e/8
__device__ __half g_kp[MR*DMODEL];
__device__ __half g_vp[MR*DMODEL];
__device__ __half g_ao[MR*DMODEL];   // attention out, merged [B,S,H*DKH]

// --------------------------- helpers ----------------------------------------
__device__ __forceinline__ unsigned smem_u32(const void* p) {
    return (unsigned)__cvta_generic_to_shared(p);
}
__device__ __forceinline__ void cpa16(unsigned dst, const void* src) {
    asm volatile("cp.async.cg.shared.global [%0], [%1], 16;" :: "r"(dst), "l"(src));
}
__device__ __forceinline__ void cpa_commit() { asm volatile("cp.async.commit_group;"); }
__device__ __forceinline__ void cpa_wait0()  { asm volatile("cp.async.wait_group 0;"); }
__device__ __forceinline__ void cpa_wait1()  { asm volatile("cp.async.wait_group 1;"); }

// D(16x8) += A(16x16) * B(16x8), f16 in, f32 accum
__device__ __forceinline__ void mma16(float* c, const unsigned* a, const unsigned* b) {
    asm volatile("mma.sync.aligned.m16n8k16.row.col.f32.f16.f16.f32 "
        "{%0,%1,%2,%3}, {%4,%5,%6,%7}, {%8,%9}, {%0,%1,%2,%3};"
        : "+f"(c[0]), "+f"(c[1]), "+f"(c[2]), "+f"(c[3])
        : "r"(a[0]), "r"(a[1]), "r"(a[2]), "r"(a[3]), "r"(b[0]), "r"(b[1]));
}
__device__ __forceinline__ void ldmx4(unsigned& r0, unsigned& r1, unsigned& r2, unsigned& r3, unsigned a) {
    asm volatile("ldmatrix.sync.aligned.m8n8.x4.shared.b16 {%0,%1,%2,%3}, [%4];"
        : "=r"(r0), "=r"(r1), "=r"(r2), "=r"(r3) : "r"(a));
}
__device__ __forceinline__ void ldmx4t(unsigned& r0, unsigned& r1, unsigned& r2, unsigned& r3, unsigned a) {
    asm volatile("ldmatrix.sync.aligned.m8n8.x4.trans.shared.b16 {%0,%1,%2,%3}, [%4];"
        : "=r"(r0), "=r"(r1), "=r"(r2), "=r"(r3) : "r"(a));
}
__device__ __forceinline__ unsigned packh2(float a, float b) {
    half2 h = __floats2half2_rn(a, b);
    return *reinterpret_cast<unsigned*>(&h);
}

// --------------------------- fp32 -> fp16 converter --------------------------
__global__ void f2h4(const float* __restrict__ s0, const float* __restrict__ s1,
                     const float* __restrict__ s2, const float* __restrict__ s3,
                     __half* d0, __half* d1, __half* d2, __half* d3, int n4)
{
    const float* s; __half* d;
    switch (blockIdx.y) {
        case 0: s = s0; d = d0; break;
        case 1: s = s1; d = d1; break;
        case 2: s = s2; d = d2; break;
        default: s = s3; d = d3; break;
    }
    for (int i = blockIdx.x*blockDim.x + threadIdx.x; i < n4; i += gridDim.x*blockDim.x) {
        float4 v = ((const float4*)s)[i];
        ((half2*)d)[2*i]   = __floats2half2_rn(v.x, v.y);
        ((half2*)d)[2*i+1] = __floats2half2_rn(v.z, v.w);
    }
}

// ---------------------------------------------------------------------------
// C = scale * A @ W^T (+bias). z = blockIdx.z selects (A, W, C, scale).
// CTA 128x128, 256 threads / 8 warps (2m x 4n), warp tile 64x32, Kt=32,
// 3-stage cp.async pipeline, ldmatrix.x4 fragment loads.
// ---------------------------------------------------------------------------
struct GemmArgs {
    const __half* A[3]; const __half* W[3]; void* C[3];
    float scale[3]; const float* bias; int split;
};

#define GLD 40   // smem row stride in halves (80B, conflict-free)
__global__ __launch_bounds__(256, 2) void gemm_h(GemmArgs ga)
{
    extern __shared__ __half sm[];
    __half* smA = sm;                 // 3 x [128][GLD]
    __half* smB = sm + 3*128*GLD;     // 3 x [128][GLD]

    const int tid = threadIdx.x, lane = tid & 31;
    const int g = lane >> 2, t = lane & 3, wid = tid >> 5;
    const int wm = (wid & 1) * 64, wn = (wid >> 1) * 32;
    const int m0 = blockIdx.y * 128, n0 = blockIdx.x * 128;
    const int z = blockIdx.z;

    const __half* Ag = ga.A[z] + (size_t)m0 * DMODEL;
    const __half* Wg = ga.W[z] + (size_t)n0 * DMODEL;
    const float scale = ga.scale[z];

    int crow[2], coff[2];
#pragma unroll
    for (int l = 0; l < 2; l++) {
        int c = tid + l*256;
        crow[l] = c >> 2; coff[l] = (c & 3) * 8;
    }

    auto issue = [&](int tile) {
        int buf = tile % 3, k0 = tile * 32;
        unsigned da = smem_u32(smA + buf*128*GLD);
        unsigned db = smem_u32(smB + buf*128*GLD);
#pragma unroll
        for (int l = 0; l < 2; l++) {
            cpa16(da + (crow[l]*GLD + coff[l])*2, Ag + (size_t)crow[l]*DMODEL + k0 + coff[l]);
            cpa16(db + (crow[l]*GLD + coff[l])*2, Wg + (size_t)crow[l]*DMODEL + k0 + coff[l]);
        }
    };
    issue(0); cpa_commit();
    issue(1); cpa_commit();

    // ldmatrix per-thread address constants
    const int arow_c = lane & 15;              // A: row within 16-row frag
    const int akh    = (lane >> 4) * 8;        // A: k-half select
    const int brow_c = ((lane >> 4) & 1) * 8 + (lane & 7);  // B: row within fn-pair
    const int bkh    = ((lane >> 3) & 1) * 8;               // B: k-half select

    float acc[4][4][4] = {};

    for (int i = 0; i < 32; i++) {
        cpa_wait1();
        __syncthreads();
        if (i + 2 < 32) issue(i + 2);
        cpa_commit();

        const unsigned abase = smem_u32(smA + (i % 3)*128*GLD);
        const unsigned bbase = smem_u32(smB + (i % 3)*128*GLD);
#pragma unroll
        for (int ks = 0; ks < 2; ks++) {
            const int k = ks * 16;
            unsigned af[4][4], bf[4][2];
#pragma unroll
            for (int fm = 0; fm < 4; fm++)
                ldmx4(af[fm][0], af[fm][1], af[fm][2], af[fm][3],
                      abase + ((wm + fm*16 + arow_c)*GLD + k + akh)*2);
#pragma unroll
            for (int p = 0; p < 2; p++) {
                unsigned r0, r1, r2, r3;
                ldmx4(r0, r1, r2, r3,
                      bbase + ((wn + p*16 + brow_c)*GLD + k + bkh)*2);
                bf[2*p][0]   = r0; bf[2*p][1]   = r1;
                bf[2*p+1][0] = r2; bf[2*p+1][1] = r3;
            }
#pragma unroll
            for (int fm = 0; fm < 4; fm++)
#pragma unroll
                for (int fn = 0; fn < 4; fn++) mma16(acc[fm][fn], af[fm], bf[fn]);
        }
        __syncthreads();
    }

#pragma unroll
    for (int fn = 0; fn < 4; fn++) {
        int n = n0 + wn + fn*8 + 2*t;
        float b0 = 0.f, b1 = 0.f;
        if (ga.bias) { b0 = ga.bias[n]; b1 = ga.bias[n+1]; }
#pragma unroll
        for (int fm = 0; fm < 4; fm++) {
#pragma unroll
            for (int rr = 0; rr < 2; rr++) {
                int m = m0 + wm + fm*16 + g + rr*8;
                float vx = acc[fm][fn][rr*2]   * scale + b0;
                float vy = acc[fm][fn][rr*2+1] * scale + b1;
                if (ga.split) {
                    int bb = m >> 11, ss = m & (SEQ-1);
                    int hh = n >> 6,  dd = n & 63;
                    __half* C = (__half*)ga.C[z];
                    *(half2*)(C + (size_t)(((bb*HEADS + hh)*SEQ) + ss)*DKH + dd) =
                        __floats2half2_rn(vx, vy);
                } else {
                    float* C = (float*)ga.C[z];
                    *(float2*)(C + (size_t)m*DMODEL + n) = make_float2(vx, vy);
                }
            }
        }
    }
}

// ---------------------------------------------------------------------------
// Flash attention fp16. Br=128 (4 warps x 32 q-rows), Bc=64, 2-stage
// cp.async K/V pipeline, exp2-domain softmax. Register diet for 3 CTAs/SM:
// P packed to fp16 right after softmax (sc dies before PV), mask loads
// scoped per stat-row, single mask base pointer.
// ---------------------------------------------------------------------------
#define FLD 72   // smem row stride in halves (144B)
#define FTS (64*FLD)
__global__ __launch_bounds__(128, 3) void flash_h(
    const __half* __restrict__ Qp, const __half* __restrict__ Kp,
    const __half* __restrict__ Vp, const int* __restrict__ mask,
    __half* __restrict__ Out)
{
    extern __shared__ __half fsm[];
    __half* Qs = fsm;                 // [128][FLD]
    __half* Ks = fsm + 2*FTS;         // 2 x [64][FLD]
    __half* Vs = fsm + 4*FTS;         // 2 x [64][FLD]

    const int tid = threadIdx.x, lane = tid & 31;
    const int g = lane >> 2, t = lane & 3, wid = tid >> 5;
    const int q0 = blockIdx.x * 128, h = blockIdx.y, b = blockIdx.z;
    const int qw = wid * 32;

    const __half* Qg = Qp + (size_t)((b*HEADS + h)*SEQ + q0)*DKH;
    const __half* Kg = Kp + (size_t)((b*HEADS + h)*SEQ)*DKH;
    const __half* Vg = Vp + (size_t)((b*HEADS + h)*SEQ)*DKH;

    // K/V tile: 64 rows x 8 chunks(16B) = 512 chunks; 4/thread
    int crow[4], coff[4];
#pragma unroll
    for (int l = 0; l < 4; l++) {
        int c = tid + l*128;
        crow[l] = c >> 3; coff[l] = (c & 7) * 8;
    }

    auto issue_kv = [&](int tile) {
        int buf = tile & 1, k0 = tile * 64;
        unsigned dk = smem_u32(Ks + buf*FTS);
        unsigned dv = smem_u32(Vs + buf*FTS);
#pragma unroll
        for (int l = 0; l < 4; l++) {
            cpa16(dk + (crow[l]*FLD + coff[l])*2, Kg + (size_t)(k0 + crow[l])*DKH + coff[l]);
            cpa16(dv + (crow[l]*FLD + coff[l])*2, Vg + (size_t)(k0 + crow[l])*DKH + coff[l]);
        }
    };
    {   // group 0: Q (128 rows = 1024 chunks, 8/thread) + K/V tile 0
        unsigned dq = smem_u32(Qs);
#pragma unroll
        for (int l = 0; l < 8; l++) {
            int c = tid + l*128;
            int r = c >> 3, cc = (c & 7) * 8;
            cpa16(dq + (r*FLD + cc)*2, Qg + (size_t)r*DKH + cc);
        }
        issue_kv(0); cpa_commit();
    }

    // ldmatrix per-thread address constants
    const int krow_c = ((lane >> 4) & 1) * 8 + (lane & 7);  // K, non-trans
    const int kkh    = ((lane >> 3) & 1) * 8;
    const int vrow_c = (lane & 7) + ((lane >> 3) & 1) * 8;  // V, trans
    const int vcol_c = (lane >> 4) * 8;

    // single mask base pointer (offsets for rb/rr are compile-time constants)
    const int* mbase = mask + (size_t)(b*SEQ + q0 + qw + g)*SEQ + 2*t;

    unsigned aq[2][4][4];
    float o[2][8][4] = {};
    float m_[2][2] = {{-1e30f,-1e30f},{-1e30f,-1e30f}};
    float l_[2][2] = {{0.f,0.f},{0.f,0.f}};

    for (int i = 0; i < 32; i++) {
        cpa_wait0();
        __syncthreads();                 // tile i ready; all reads of other buf done
        if (i + 1 < 32) { issue_kv(i + 1); cpa_commit(); }

        if (i == 0) {   // Q frags -> registers (once)
#pragma unroll
            for (int rb = 0; rb < 2; rb++)
#pragma unroll
                for (int ks = 0; ks < 4; ks++) {
                    const int r = qw + rb*16 + g, k = ks*16;
                    aq[rb][ks][0] = *(const unsigned*)&Qs[r*FLD + k + 2*t];
                    aq[rb][ks][1] = *(const unsigned*)&Qs[(r+8)*FLD + k + 2*t];
                    aq[rb][ks][2] = *(const unsigned*)&Qs[r*FLD + k + 8 + 2*t];
                    aq[rb][ks][3] = *(const unsigned*)&Qs[(r+8)*FLD + k + 8 + 2*t];
                }
        }

        const unsigned kbase = smem_u32(Ks + (i & 1)*FTS);
        const unsigned vbase = smem_u32(Vs + (i & 1)*FTS);

        // S = Q K^T; each ldmatrix.x4 feeds 4 MMAs (2 row-frags x 2 cols)
        float sc[2][8][4] = {};
#pragma unroll
        for (int ks = 0; ks < 4; ks++) {
            const int k = ks*16;
#pragma unroll
            for (int p = 0; p < 4; p++) {
                unsigned r0, r1, r2, r3;
                unsigned addr = kbase + ((p*16 + krow_c)*FLD + k + kkh)*2;
                ldmx4(r0, r1, r2, r3, addr);
                unsigned b0[2] = {r0, r1}, b1[2] = {r2, r3};
#pragma unroll
                for (int rb = 0; rb < 2; rb++) {
                    mma16(sc[rb][2*p],   aq[rb][ks], b0);
                    mma16(sc[rb][2*p+1], aq[rb][ks], b1);
                }
            }
        }

        // mask + online softmax, scoped per stat-row (short mask live ranges)
#pragma unroll
        for (int rb = 0; rb < 2; rb++)
#pragma unroll
            for (int rr = 0; rr < 2; rr++) {
                {   // mask for this stat-row only (8 int2, 16 regs, dies here)
                    const int* mr = mbase + (size_t)(rb*16 + rr*8)*SEQ + i*64;
#pragma unroll
                    for (int fn = 0; fn < 8; fn++) {
                        int2 mv = *(const int2*)(mr + fn*8);
                        if (mv.x == 0) sc[rb][fn][rr*2]   = -1e30f;
                        if (mv.y == 0) sc[rb][fn][rr*2+1] = -1e30f;
                    }
                }
                float rmax = -1e30f;
#pragma unroll
                for (int fn = 0; fn < 8; fn++)
                    rmax = fmaxf(rmax, fmaxf(sc[rb][fn][rr*2], sc[rb][fn][rr*2+1]));
                rmax = fmaxf(rmax, __shfl_xor_sync(0xffffffffu, rmax, 1));
                rmax = fmaxf(rmax, __shfl_xor_sync(0xffffffffu, rmax, 2));
                float mn = fmaxf(m_[rb][rr], rmax);
                float alpha = exp2f(m_[rb][rr] - mn);
                float rsum = 0.f;
#pragma unroll
                for (int fn = 0; fn < 8; fn++) {
                    sc[rb][fn][rr*2]   = exp2f(sc[rb][fn][rr*2]   - mn);
                    sc[rb][fn][rr*2+1] = exp2f(sc[rb][fn][rr*2+1] - mn);
                    rsum += sc[rb][fn][rr*2] + sc[rb][fn][rr*2+1];
                }
                rsum += __shfl_xor_sync(0xffffffffu, rsum, 1);
                rsum += __shfl_xor_sync(0xffffffffu, rsum, 2);
                l_[rb][rr] = l_[rb][rr]*alpha + rsum;
                m_[rb][rr] = mn;
#pragma unroll
                for (int fn = 0; fn < 8; fn++) {
                    o[rb][fn][rr*2]   *= alpha;
                    o[rb][fn][rr*2+1] *= alpha;
                }
            }

        // pack P to fp16 NOW — sc dead before the PV loop
        unsigned ap[2][4][4];
#pragma unroll
        for (int rb = 0; rb < 2; rb++)
#pragma unroll
            for (int ks = 0; ks < 4; ks++) {
                ap[rb][ks][0] = packh2(sc[rb][2*ks][0],   sc[rb][2*ks][1]);
                ap[rb][ks][1] = packh2(sc[rb][2*ks][2],   sc[rb][2*ks][3]);
                ap[rb][ks][2] = packh2(sc[rb][2*ks+1][0], sc[rb][2*ks+1][1]);
                ap[rb][ks][3] = packh2(sc[rb][2*ks+1][2], sc[rb][2*ks+1][3]);
            }

        // O += P @ V; each ldmatrix.x4.trans feeds 4 MMAs
#pragma unroll
        for (int ks = 0; ks < 4; ks++) {
            const int k = ks*16;
#pragma unroll
            for (int fp = 0; fp < 4; fp++) {
                unsigned r0, r1, r2, r3;
                unsigned addr = vbase + ((k + vrow_c)*FLD + fp*16 + vcol_c)*2;
                ldmx4t(r0, r1, r2, r3, addr);
                unsigned b0[2] = {r0, r1}, b1[2] = {r2, r3};
#pragma unroll
                for (int rb = 0; rb < 2; rb++) {
                    mma16(o[rb][2*fp],   ap[rb][ks], b0);
                    mma16(o[rb][2*fp+1], ap[rb][ks], b1);
                }
            }
        }
    }

    // normalize + half store, merged [B,S, h*64+d]
#pragma unroll
    for (int rb = 0; rb < 2; rb++)
#pragma unroll
        for (int rr = 0; rr < 2; rr++) {
            float inv = 1.0f / l_[rb][rr];
            int row = q0 + qw + rb*16 + rr*8 + g;
            __half* op = Out + (size_t)(b*SEQ + row)*DMODEL + h*DKH + 2*t;
#pragma unroll
            for (int fn = 0; fn < 8; fn++)
                *(half2*)(op + fn*8) =
                    __floats2half2_rn(o[rb][fn][rr*2]*inv, o[rb][fn][rr*2+1]*inv);
        }
}

// ---------------------------------------------------------------------------
extern "C" void kernel_launch(void* const* d_in, const int* in_sizes, int n_in,
                              void* d_out, int out_size)
{
    const float* q  = (const float*)d_in[0];
    const float* k  = (const float*)d_in[1];
    const float* v  = (const float*)d_in[2];
    const int*   mk = (const int*)  d_in[3];
    const float* wq = (const float*)d_in[4];
    const float* wk = (const float*)d_in[5];
    const float* wv = (const float*)d_in[6];
    const float* wo = (const float*)d_in[7];
    const float* bo = (const float*)d_in[8];
    float* out = (float*)d_out;

    __half *qh, *kh, *vh, *wqh, *wkh, *wvh, *woh, *qp, *kp, *vp, *ao;
    cudaGetSymbolAddress((void**)&qh,  g_qh);
    cudaGetSymbolAddress((void**)&kh,  g_kh);
    cudaGetSymbolAddress((void**)&vh,  g_vh);
    cudaGetSymbolAddress((void**)&wqh, g_wqh);
    cudaGetSymbolAddress((void**)&wkh, g_wkh);
    cudaGetSymbolAddress((void**)&wvh, g_wvh);
    cudaGetSymbolAddress((void**)&woh, g_woh);
    cudaGetSymbolAddress((void**)&qp,  g_qp);
    cudaGetSymbolAddress((void**)&kp,  g_kp);
    cudaGetSymbolAddress((void**)&vp,  g_vp);
    cudaGetSymbolAddress((void**)&ao,  g_ao);

    const int gemm_smem  = 6 * 128 * GLD * 2;      // 61440 B
    const int flash_smem = 6 * FTS * 2;            // 55296 B
    cudaFuncSetAttribute(gemm_h,  cudaFuncAttributeMaxDynamicSharedMemorySize, gemm_smem);
    cudaFuncSetAttribute(flash_h, cudaFuncAttributeMaxDynamicSharedMemorySize, flash_smem);

    // fp32 -> fp16 conversions
    f2h4<<<dim3(512, 3), 256>>>(q, k, v, nullptr, qh, kh, vh, nullptr, MR*DMODEL/4);
    f2h4<<<dim3(128, 4), 256>>>(wq, wk, wv, wo, wqh, wkh, wvh, woh, DMODEL*DMODEL/4);

    // fused QKV projections; q scale = log2(e)/sqrt(64) for exp2-domain softmax
    GemmArgs pa;
    pa.A[0] = qh;  pa.A[1] = kh;  pa.A[2] = vh;
    pa.W[0] = wqh; pa.W[1] = wkh; pa.W[2] = wvh;
    pa.C[0] = qp;  pa.C[1] = kp;  pa.C[2] = vp;
    pa.scale[0] = 0.125f * 1.44269504088896f; pa.scale[1] = 1.0f; pa.scale[2] = 1.0f;
    pa.bias = nullptr; pa.split = 1;
    gemm_h<<<dim3(DMODEL/128, MR/128, 3), 256, gemm_smem>>>(pa);

    flash_h<<<dim3(SEQ/128, HEADS, BATCH), 128, flash_smem>>>(qp, kp, vp, mk, ao);

    // output projection + bias
    GemmArgs oa;
    oa.A[0] = ao; oa.A[1] = nullptr; oa.A[2] = nullptr;
    oa.W[0] = woh; oa.W[1] = nullptr; oa.W[2] = nullptr;
    oa.C[0] = out; oa.C[1] = nullptr; oa.C[2] = nullptr;
    oa.scale[0] = 1.0f; oa.scale[1] = 1.0f; oa.scale[2] = 1.0f;
    oa.bias = bo; oa.split = 0;
    gemm_h<<<dim3(DMODEL/128, MR/128, 1), 256, gemm_smem>>>(oa);
}

// round 14
// speedup vs baseline: 1.0768x; 1.0768x over previous
#include <cuda_runtime.h>
#include <cuda_fp16.h>

#define DMODEL 1024
#define HEADS  16
#define DKH    64
#define BATCH  2
#define SEQ    2048
#define MR     (BATCH*SEQ)   // 4096 rows

// --------------------------- device scratch (no allocs) ---------------------
__device__ __half g_qh[MR*DMODEL];   // half copies of inputs
__device__ __half g_kh[MR*DMODEL];
__device__ __half g_vh[MR*DMODEL];
__device__ __half g_wqh[DMODEL*DMODEL];
__device__ __half g_wkh[DMODEL*DMODEL];
__device__ __half g_wvh[DMODEL*DMODEL];
__device__ __half g_woh[DMODEL*DMODEL];
__device__ __half g_qp[MR*DMODEL];   // projected, head-split [B,H,S,DKH], q scaled by log2e/8
__device__ __half g_kp[MR*DMODEL];
__device__ __half g_vp[MR*DMODEL];
__device__ __half g_ao[MR*DMODEL];   // attention out, merged [B,S,H*DKH]
__device__ unsigned g_rf[MR];        // per (b,q) row: bit i = k-tile i all-ones

// --------------------------- helpers ----------------------------------------
__device__ __forceinline__ unsigned smem_u32(const void* p) {
    return (unsigned)__cvta_generic_to_shared(p);
}
__device__ __forceinline__ void cpa16(unsigned dst, const void* src) {
    asm volatile("cp.async.cg.shared.global [%0], [%1], 16;" :: "r"(dst), "l"(src));
}
__device__ __forceinline__ void cpa_commit() { asm volatile("cp.async.commit_group;"); }
__device__ __forceinline__ void cpa_wait0()  { asm volatile("cp.async.wait_group 0;"); }
__device__ __forceinline__ void cpa_wait1()  { asm volatile("cp.async.wait_group 1;"); }

// D(16x8) += A(16x16) * B(16x8), f16 in, f32 accum
__device__ __forceinline__ void mma16(float* c, const unsigned* a, const unsigned* b) {
    asm volatile("mma.sync.aligned.m16n8k16.row.col.f32.f16.f16.f32 "
        "{%0,%1,%2,%3}, {%4,%5,%6,%7}, {%8,%9}, {%0,%1,%2,%3};"
        : "+f"(c[0]), "+f"(c[1]), "+f"(c[2]), "+f"(c[3])
        : "r"(a[0]), "r"(a[1]), "r"(a[2]), "r"(a[3]), "r"(b[0]), "r"(b[1]));
}
__device__ __forceinline__ void ldmx4(unsigned& r0, unsigned& r1, unsigned& r2, unsigned& r3, unsigned a) {
    asm volatile("ldmatrix.sync.aligned.m8n8.x4.shared.b16 {%0,%1,%2,%3}, [%4];"
        : "=r"(r0), "=r"(r1), "=r"(r2), "=r"(r3) : "r"(a));
}
__device__ __forceinline__ void ldmx4t(unsigned& r0, unsigned& r1, unsigned& r2, unsigned& r3, unsigned a) {
    asm volatile("ldmatrix.sync.aligned.m8n8.x4.trans.shared.b16 {%0,%1,%2,%3}, [%4];"
        : "=r"(r0), "=r"(r1), "=r"(r2), "=r"(r3) : "r"(a));
}
__device__ __forceinline__ unsigned packh2(float a, float b) {
    half2 h = __floats2half2_rn(a, b);
    return *reinterpret_cast<unsigned*>(&h);
}

// --------------------------- fp32 -> fp16 converter --------------------------
__global__ void f2h4(const float* __restrict__ s0, const float* __restrict__ s1,
                     const float* __restrict__ s2, const float* __restrict__ s3,
                     __half* d0, __half* d1, __half* d2, __half* d3, int n4)
{
    const float* s; __half* d;
    switch (blockIdx.y) {
        case 0: s = s0; d = d0; break;
        case 1: s = s1; d = d1; break;
        case 2: s = s2; d = d2; break;
        default: s = s3; d = d3; break;
    }
    for (int i = blockIdx.x*blockDim.x + threadIdx.x; i < n4; i += gridDim.x*blockDim.x) {
        float4 v = ((const float4*)s)[i];
        ((half2*)d)[2*i]   = __floats2half2_rn(v.x, v.y);
        ((half2*)d)[2*i+1] = __floats2half2_rn(v.z, v.w);
    }
}

// --------------------------- mask row-flag prepass ---------------------------
// One warp per mask row (b*SEQ + q). Lane l reduces k-tile l (64 ints);
// ballot packs 32 tile-flags into one word.
__global__ void rowflags(const int* __restrict__ m, unsigned* __restrict__ out)
{
    int row = blockIdx.x * (blockDim.x >> 5) + (threadIdx.x >> 5);
    int lane = threadIdx.x & 31;
    const int4* p = (const int4*)(m + (size_t)row*SEQ + lane*64);
    int all = 1;
#pragma unroll
    for (int j = 0; j < 16; j++) {
        int4 v = p[j];
        all &= (v.x && v.y && v.z && v.w) ? 1 : 0;
    }
    unsigned bits = __ballot_sync(0xffffffffu, all);
    if (lane == 0) out[row] = bits;
}

// ---------------------------------------------------------------------------
// C = scale * A @ W^T (+bias). z = blockIdx.z selects (A, W, C, scale).
// CTA 128x128, 256 threads / 8 warps (2m x 4n), warp tile 64x32, Kt=32,
// 3-stage cp.async pipeline, ldmatrix.x4 fragment loads.
// ---------------------------------------------------------------------------
struct GemmArgs {
    const __half* A[3]; const __half* W[3]; void* C[3];
    float scale[3]; const float* bias; int split;
};

#define GLD 40   // smem row stride in halves (80B, conflict-free)
__global__ __launch_bounds__(256, 2) void gemm_h(GemmArgs ga)
{
    extern __shared__ __half sm[];
    __half* smA = sm;                 // 3 x [128][GLD]
    __half* smB = sm + 3*128*GLD;     // 3 x [128][GLD]

    const int tid = threadIdx.x, lane = tid & 31;
    const int g = lane >> 2, t = lane & 3, wid = tid >> 5;
    const int wm = (wid & 1) * 64, wn = (wid >> 1) * 32;
    const int m0 = blockIdx.y * 128, n0 = blockIdx.x * 128;
    const int z = blockIdx.z;

    const __half* Ag = ga.A[z] + (size_t)m0 * DMODEL;
    const __half* Wg = ga.W[z] + (size_t)n0 * DMODEL;
    const float scale = ga.scale[z];

    int crow[2], coff[2];
#pragma unroll
    for (int l = 0; l < 2; l++) {
        int c = tid + l*256;
        crow[l] = c >> 2; coff[l] = (c & 3) * 8;
    }

    auto issue = [&](int tile) {
        int buf = tile % 3, k0 = tile * 32;
        unsigned da = smem_u32(smA + buf*128*GLD);
        unsigned db = smem_u32(smB + buf*128*GLD);
#pragma unroll
        for (int l = 0; l < 2; l++) {
            cpa16(da + (crow[l]*GLD + coff[l])*2, Ag + (size_t)crow[l]*DMODEL + k0 + coff[l]);
            cpa16(db + (crow[l]*GLD + coff[l])*2, Wg + (size_t)crow[l]*DMODEL + k0 + coff[l]);
        }
    };
    issue(0); cpa_commit();
    issue(1); cpa_commit();

    // ldmatrix per-thread address constants
    const int arow_c = lane & 15;              // A: row within 16-row frag
    const int akh    = (lane >> 4) * 8;        // A: k-half select
    const int brow_c = ((lane >> 4) & 1) * 8 + (lane & 7);  // B: row within fn-pair
    const int bkh    = ((lane >> 3) & 1) * 8;               // B: k-half select

    float acc[4][4][4] = {};

    for (int i = 0; i < 32; i++) {
        cpa_wait1();
        __syncthreads();
        if (i + 2 < 32) issue(i + 2);
        cpa_commit();

        const unsigned abase = smem_u32(smA + (i % 3)*128*GLD);
        const unsigned bbase = smem_u32(smB + (i % 3)*128*GLD);
#pragma unroll
        for (int ks = 0; ks < 2; ks++) {
            const int k = ks * 16;
            unsigned af[4][4], bf[4][2];
#pragma unroll
            for (int fm = 0; fm < 4; fm++)
                ldmx4(af[fm][0], af[fm][1], af[fm][2], af[fm][3],
                      abase + ((wm + fm*16 + arow_c)*GLD + k + akh)*2);
#pragma unroll
            for (int p = 0; p < 2; p++) {
                unsigned r0, r1, r2, r3;
                ldmx4(r0, r1, r2, r3,
                      bbase + ((wn + p*16 + brow_c)*GLD + k + bkh)*2);
                bf[2*p][0]   = r0; bf[2*p][1]   = r1;
                bf[2*p+1][0] = r2; bf[2*p+1][1] = r3;
            }
#pragma unroll
            for (int fm = 0; fm < 4; fm++)
#pragma unroll
                for (int fn = 0; fn < 4; fn++) mma16(acc[fm][fn], af[fm], bf[fn]);
        }
        __syncthreads();
    }

#pragma unroll
    for (int fn = 0; fn < 4; fn++) {
        int n = n0 + wn + fn*8 + 2*t;
        float b0 = 0.f, b1 = 0.f;
        if (ga.bias) { b0 = ga.bias[n]; b1 = ga.bias[n+1]; }
#pragma unroll
        for (int fm = 0; fm < 4; fm++) {
#pragma unroll
            for (int rr = 0; rr < 2; rr++) {
                int m = m0 + wm + fm*16 + g + rr*8;
                float vx = acc[fm][fn][rr*2]   * scale + b0;
                float vy = acc[fm][fn][rr*2+1] * scale + b1;
                if (ga.split) {
                    int bb = m >> 11, ss = m & (SEQ-1);
                    int hh = n >> 6,  dd = n & 63;
                    __half* C = (__half*)ga.C[z];
                    *(half2*)(C + (size_t)(((bb*HEADS + hh)*SEQ) + ss)*DKH + dd) =
                        __floats2half2_rn(vx, vy);
                } else {
                    float* C = (float*)ga.C[z];
                    *(float2*)(C + (size_t)m*DMODEL + n) = make_float2(vx, vy);
                }
            }
        }
    }
}

// ---------------------------------------------------------------------------
// Flash attention fp16 (round-12 structure, 255 regs / 2 CTAs per SM).
// Br=128 (4 warps x 32 q-rows), Bc=64, 2-stage cp.async K/V pipeline,
// exp2-domain softmax, P packed lazily in PV loop. Mask via per-row tile
// bitmask: one word per stat-row loaded once; detailed int2 loads only on
// tiles with zeros (slow path, normally never taken).
// ---------------------------------------------------------------------------
#define FLD 72   // smem row stride in halves (144B)
#define FTS (64*FLD)
__global__ __launch_bounds__(128, 2) void flash_h(
    const __half* __restrict__ Qp, const __half* __restrict__ Kp,
    const __half* __restrict__ Vp, const int* __restrict__ mask,
    const unsigned* __restrict__ rf, __half* __restrict__ Out)
{
    extern __shared__ __half fsm[];
    __half* Qs = fsm;                 // [128][FLD]
    __half* Ks = fsm + 2*FTS;         // 2 x [64][FLD]
    __half* Vs = fsm + 4*FTS;         // 2 x [64][FLD]

    const int tid = threadIdx.x, lane = tid & 31;
    const int g = lane >> 2, t = lane & 3, wid = tid >> 5;
    const int q0 = blockIdx.x * 128, h = blockIdx.y, b = blockIdx.z;
    const int qw = wid * 32;

    const __half* Qg = Qp + (size_t)((b*HEADS + h)*SEQ + q0)*DKH;
    const __half* Kg = Kp + (size_t)((b*HEADS + h)*SEQ)*DKH;
    const __half* Vg = Vp + (size_t)((b*HEADS + h)*SEQ)*DKH;

    // K/V tile: 64 rows x 8 chunks(16B) = 512 chunks; 4/thread
    int crow[4], coff[4];
#pragma unroll
    for (int l = 0; l < 4; l++) {
        int c = tid + l*128;
        crow[l] = c >> 3; coff[l] = (c & 7) * 8;
    }

    auto issue_kv = [&](int tile) {
        int buf = tile & 1, k0 = tile * 64;
        unsigned dk = smem_u32(Ks + buf*FTS);
        unsigned dv = smem_u32(Vs + buf*FTS);
#pragma unroll
        for (int l = 0; l < 4; l++) {
            cpa16(dk + (crow[l]*FLD + coff[l])*2, Kg + (size_t)(k0 + crow[l])*DKH + coff[l]);
            cpa16(dv + (crow[l]*FLD + coff[l])*2, Vg + (size_t)(k0 + crow[l])*DKH + coff[l]);
        }
    };
    {   // group 0: Q (128 rows = 1024 chunks, 8/thread) + K/V tile 0
        unsigned dq = smem_u32(Qs);
#pragma unroll
        for (int l = 0; l < 8; l++) {
            int c = tid + l*128;
            int r = c >> 3, cc = (c & 7) * 8;
            cpa16(dq + (r*FLD + cc)*2, Qg + (size_t)r*DKH + cc);
        }
        issue_kv(0); cpa_commit();
    }

    // ldmatrix per-thread address constants
    const int krow_c = ((lane >> 4) & 1) * 8 + (lane & 7);  // K, non-trans
    const int kkh    = ((lane >> 3) & 1) * 8;
    const int vrow_c = (lane & 7) + ((lane >> 3) & 1) * 8;  // V, trans
    const int vcol_c = (lane >> 4) * 8;

    // mask base + per-stat-row tile bitmasks (one word per row, loaded once)
    const int* mbase = mask + (size_t)(b*SEQ + q0 + qw + g)*SEQ + 2*t;
    unsigned rmb[2][2];
#pragma unroll
    for (int rb = 0; rb < 2; rb++)
#pragma unroll
        for (int rr = 0; rr < 2; rr++)
            rmb[rb][rr] = rf[b*SEQ + q0 + qw + rb*16 + rr*8 + g];

    unsigned aq[2][4][4];
    float o[2][8][4] = {};
    float m_[2][2] = {{-1e30f,-1e30f},{-1e30f,-1e30f}};
    float l_[2][2] = {{0.f,0.f},{0.f,0.f}};

    for (int i = 0; i < 32; i++) {
        cpa_wait0();
        __syncthreads();                 // tile i ready; all reads of other buf done
        if (i + 1 < 32) { issue_kv(i + 1); cpa_commit(); }

        if (i == 0) {   // Q frags -> registers (once)
#pragma unroll
            for (int rb = 0; rb < 2; rb++)
#pragma unroll
                for (int ks = 0; ks < 4; ks++) {
                    const int r = qw + rb*16 + g, k = ks*16;
                    aq[rb][ks][0] = *(const unsigned*)&Qs[r*FLD + k + 2*t];
                    aq[rb][ks][1] = *(const unsigned*)&Qs[(r+8)*FLD + k + 2*t];
                    aq[rb][ks][2] = *(const unsigned*)&Qs[r*FLD + k + 8 + 2*t];
                    aq[rb][ks][3] = *(const unsigned*)&Qs[(r+8)*FLD + k + 8 + 2*t];
                }
        }

        const unsigned kbase = smem_u32(Ks + (i & 1)*FTS);
        const unsigned vbase = smem_u32(Vs + (i & 1)*FTS);

        // S = Q K^T; each ldmatrix.x4 feeds 4 MMAs (2 row-frags x 2 cols)
        float sc[2][8][4] = {};
#pragma unroll
        for (int ks = 0; ks < 4; ks++) {
            const int k = ks*16;
#pragma unroll
            for (int p = 0; p < 4; p++) {
                unsigned r0, r1, r2, r3;
                unsigned addr = kbase + ((p*16 + krow_c)*FLD + k + kkh)*2;
                ldmx4(r0, r1, r2, r3, addr);
                unsigned b0[2] = {r0, r1}, b1[2] = {r2, r3};
#pragma unroll
                for (int rb = 0; rb < 2; rb++) {
                    mma16(sc[rb][2*p],   aq[rb][ks], b0);
                    mma16(sc[rb][2*p+1], aq[rb][ks], b1);
                }
            }
        }

        // mask: bit test per stat-row; detailed loads only if tile has zeros
#pragma unroll
        for (int rb = 0; rb < 2; rb++)
#pragma unroll
            for (int rr = 0; rr < 2; rr++) {
                if (!((rmb[rb][rr] >> i) & 1u)) {
                    const int* mr = mbase + (size_t)(rb*16 + rr*8)*SEQ + i*64;
#pragma unroll
                    for (int fn = 0; fn < 8; fn++) {
                        int2 mv = *(const int2*)(mr + fn*8);
                        if (mv.x == 0) sc[rb][fn][rr*2]   = -1e30f;
                        if (mv.y == 0) sc[rb][fn][rr*2+1] = -1e30f;
                    }
                }
            }

        // online softmax (exp2 domain)
#pragma unroll
        for (int rb = 0; rb < 2; rb++)
#pragma unroll
            for (int rr = 0; rr < 2; rr++) {
                float rmax = -1e30f;
#pragma unroll
                for (int fn = 0; fn < 8; fn++)
                    rmax = fmaxf(rmax, fmaxf(sc[rb][fn][rr*2], sc[rb][fn][rr*2+1]));
                rmax = fmaxf(rmax, __shfl_xor_sync(0xffffffffu, rmax, 1));
                rmax = fmaxf(rmax, __shfl_xor_sync(0xffffffffu, rmax, 2));
                float mn = fmaxf(m_[rb][rr], rmax);
                float alpha = exp2f(m_[rb][rr] - mn);
                float rsum = 0.f;
#pragma unroll
                for (int fn = 0; fn < 8; fn++) {
                    sc[rb][fn][rr*2]   = exp2f(sc[rb][fn][rr*2]   - mn);
                    sc[rb][fn][rr*2+1] = exp2f(sc[rb][fn][rr*2+1] - mn);
                    rsum += sc[rb][fn][rr*2] + sc[rb][fn][rr*2+1];
                }
                rsum += __shfl_xor_sync(0xffffffffu, rsum, 1);
                rsum += __shfl_xor_sync(0xffffffffu, rsum, 2);
                l_[rb][rr] = l_[rb][rr]*alpha + rsum;
                m_[rb][rr] = mn;
#pragma unroll
                for (int fn = 0; fn < 8; fn++) {
                    o[rb][fn][rr*2]   *= alpha;
                    o[rb][fn][rr*2+1] *= alpha;
                }
            }

        // O += P @ V; P packed lazily per ks (round-12 structure)
#pragma unroll
        for (int ks = 0; ks < 4; ks++) {
            const int k = ks*16;
            unsigned ap[2][4];
#pragma unroll
            for (int rb = 0; rb < 2; rb++) {
                ap[rb][0] = packh2(sc[rb][2*ks][0],   sc[rb][2*ks][1]);
                ap[rb][1] = packh2(sc[rb][2*ks][2],   sc[rb][2*ks][3]);
                ap[rb][2] = packh2(sc[rb][2*ks+1][0], sc[rb][2*ks+1][1]);
                ap[rb][3] = packh2(sc[rb][2*ks+1][2], sc[rb][2*ks+1][3]);
            }
#pragma unroll
            for (int fp = 0; fp < 4; fp++) {
                unsigned r0, r1, r2, r3;
                unsigned addr = vbase + ((k + vrow_c)*FLD + fp*16 + vcol_c)*2;
                ldmx4t(r0, r1, r2, r3, addr);
                unsigned b0[2] = {r0, r1}, b1[2] = {r2, r3};
#pragma unroll
                for (int rb = 0; rb < 2; rb++) {
                    mma16(o[rb][2*fp],   ap[rb], b0);
                    mma16(o[rb][2*fp+1], ap[rb], b1);
                }
            }
        }
    }

    // normalize + half store, merged [B,S, h*64+d]
#pragma unroll
    for (int rb = 0; rb < 2; rb++)
#pragma unroll
        for (int rr = 0; rr < 2; rr++) {
            float inv = 1.0f / l_[rb][rr];
            int row = q0 + qw + rb*16 + rr*8 + g;
            __half* op = Out + (size_t)(b*SEQ + row)*DMODEL + h*DKH + 2*t;
#pragma unroll
            for (int fn = 0; fn < 8; fn++)
                *(half2*)(op + fn*8) =
                    __floats2half2_rn(o[rb][fn][rr*2]*inv, o[rb][fn][rr*2+1]*inv);
        }
}

// ---------------------------------------------------------------------------
extern "C" void kernel_launch(void* const* d_in, const int* in_sizes, int n_in,
                              void* d_out, int out_size)
{
    const float* q  = (const float*)d_in[0];
    const float* k  = (const float*)d_in[1];
    const float* v  = (const float*)d_in[2];
    const int*   mk = (const int*)  d_in[3];
    const float* wq = (const float*)d_in[4];
    const float* wk = (const float*)d_in[5];
    const float* wv = (const float*)d_in[6];
    const float* wo = (const float*)d_in[7];
    const float* bo = (const float*)d_in[8];
    float* out = (float*)d_out;

    __half *qh, *kh, *vh, *wqh, *wkh, *wvh, *woh, *qp, *kp, *vp, *ao;
    unsigned* rfp;
    cudaGetSymbolAddress((void**)&qh,  g_qh);
    cudaGetSymbolAddress((void**)&kh,  g_kh);
    cudaGetSymbolAddress((void**)&vh,  g_vh);
    cudaGetSymbolAddress((void**)&wqh, g_wqh);
    cudaGetSymbolAddress((void**)&wkh, g_wkh);
    cudaGetSymbolAddress((void**)&wvh, g_wvh);
    cudaGetSymbolAddress((void**)&woh, g_woh);
    cudaGetSymbolAddress((void**)&qp,  g_qp);
    cudaGetSymbolAddress((void**)&kp,  g_kp);
    cudaGetSymbolAddress((void**)&vp,  g_vp);
    cudaGetSymbolAddress((void**)&ao,  g_ao);
    cudaGetSymbolAddress((void**)&rfp, g_rf);

    const int gemm_smem  = 6 * 128 * GLD * 2;      // 61440 B
    const int flash_smem = 6 * FTS * 2;            // 55296 B
    cudaFuncSetAttribute(gemm_h,  cudaFuncAttributeMaxDynamicSharedMemorySize, gemm_smem);
    cudaFuncSetAttribute(flash_h, cudaFuncAttributeMaxDynamicSharedMemorySize, flash_smem);

    // fp32 -> fp16 conversions + mask row-flag prepass
    f2h4<<<dim3(512, 3), 256>>>(q, k, v, nullptr, qh, kh, vh, nullptr, MR*DMODEL/4);
    f2h4<<<dim3(128, 4), 256>>>(wq, wk, wv, wo, wqh, wkh, wvh, woh, DMODEL*DMODEL/4);
    rowflags<<<MR/8, 256>>>(mk, rfp);   // 8 warps/block, one warp per row

    // fused QKV projections; q scale = log2(e)/sqrt(64) for exp2-domain softmax
    GemmArgs pa;
    pa.A[0] = qh;  pa.A[1] = kh;  pa.A[2] = vh;
    pa.W[0] = wqh; pa.W[1] = wkh; pa.W[2] = wvh;
    pa.C[0] = qp;  pa.C[1] = kp;  pa.C[2] = vp;
    pa.scale[0] = 0.125f * 1.44269504088896f; pa.scale[1] = 1.0f; pa.scale[2] = 1.0f;
    pa.bias = nullptr; pa.split = 1;
    gemm_h<<<dim3(DMODEL/128, MR/128, 3), 256, gemm_smem>>>(pa);

    flash_h<<<dim3(SEQ/128, HEADS, BATCH), 128, flash_smem>>>(qp, kp, vp, mk, rfp, ao);

    // output projection + bias
    GemmArgs oa;
    oa.A[0] = ao; oa.A[1] = nullptr; oa.A[2] = nullptr;
    oa.W[0] = woh; oa.W[1] = nullptr; oa.W[2] = nullptr;
    oa.C[0] = out; oa.C[1] = nullptr; oa.C[2] = nullptr;
    oa.scale[0] = 1.0f; oa.scale[1] = 1.0f; oa.scale[2] = 1.0f;
    oa.bias = bo; oa.split = 0;
    gemm_h<<<dim3(DMODEL/128, MR/128, 1), 256, gemm_smem>>>(oa);
}

// round 15
// speedup vs baseline: 1.6234x; 1.5076x over previous
#include <cuda_runtime.h>
#include <cuda_fp16.h>

#define DMODEL 1024
#define HEADS  16
#define DKH    64
#define BATCH  2
#define SEQ    2048
#define MR     (BATCH*SEQ)   // 4096 rows

// --------------------------- device scratch (no allocs) ---------------------
__device__ __half g_qh[MR*DMODEL];   // half copies of inputs
__device__ __half g_kh[MR*DMODEL];
__device__ __half g_vh[MR*DMODEL];
__device__ __half g_wqh[DMODEL*DMODEL];
__device__ __half g_wkh[DMODEL*DMODEL];
__device__ __half g_wvh[DMODEL*DMODEL];
__device__ __half g_woh[DMODEL*DMODEL];
__device__ __half g_qp[MR*DMODEL];   // projected, head-split [B,H,S,DKH], q scaled by log2e/8
__device__ __half g_kp[MR*DMODEL];
__device__ __half g_vp[MR*DMODEL];
__device__ __half g_ao[MR*DMODEL];   // attention out, merged [B,S,H*DKH]
__device__ unsigned g_rf[MR];        // per (b,q) row: bit i = k-tile i all-ones

// --------------------------- helpers ----------------------------------------
__device__ __forceinline__ unsigned smem_u32(const void* p) {
    return (unsigned)__cvta_generic_to_shared(p);
}
__device__ __forceinline__ void cpa16(unsigned dst, const void* src) {
    asm volatile("cp.async.cg.shared.global [%0], [%1], 16;" :: "r"(dst), "l"(src));
}
__device__ __forceinline__ void cpa_commit() { asm volatile("cp.async.commit_group;"); }
__device__ __forceinline__ void cpa_wait0()  { asm volatile("cp.async.wait_group 0;"); }
__device__ __forceinline__ void cpa_wait1()  { asm volatile("cp.async.wait_group 1;"); }

// D(16x8) += A(16x16) * B(16x8), f16 in, f32 accum
__device__ __forceinline__ void mma16(float* c, const unsigned* a, const unsigned* b) {
    asm volatile("mma.sync.aligned.m16n8k16.row.col.f32.f16.f16.f32 "
        "{%0,%1,%2,%3}, {%4,%5,%6,%7}, {%8,%9}, {%0,%1,%2,%3};"
        : "+f"(c[0]), "+f"(c[1]), "+f"(c[2]), "+f"(c[3])
        : "r"(a[0]), "r"(a[1]), "r"(a[2]), "r"(a[3]), "r"(b[0]), "r"(b[1]));
}
__device__ __forceinline__ void ldmx4(unsigned& r0, unsigned& r1, unsigned& r2, unsigned& r3, unsigned a) {
    asm volatile("ldmatrix.sync.aligned.m8n8.x4.shared.b16 {%0,%1,%2,%3}, [%4];"
        : "=r"(r0), "=r"(r1), "=r"(r2), "=r"(r3) : "r"(a));
}
__device__ __forceinline__ void ldmx4t(unsigned& r0, unsigned& r1, unsigned& r2, unsigned& r3, unsigned a) {
    asm volatile("ldmatrix.sync.aligned.m8n8.x4.trans.shared.b16 {%0,%1,%2,%3}, [%4];"
        : "=r"(r0), "=r"(r1), "=r"(r2), "=r"(r3) : "r"(a));
}
__device__ __forceinline__ unsigned packh2(float a, float b) {
    half2 h = __floats2half2_rn(a, b);
    return *reinterpret_cast<unsigned*>(&h);
}

// --------------------------- fp32 -> fp16 converter --------------------------
__global__ void f2h4(const float* __restrict__ s0, const float* __restrict__ s1,
                     const float* __restrict__ s2, const float* __restrict__ s3,
                     __half* d0, __half* d1, __half* d2, __half* d3, int n4)
{
    const float* s; __half* d;
    switch (blockIdx.y) {
        case 0: s = s0; d = d0; break;
        case 1: s = s1; d = d1; break;
        case 2: s = s2; d = d2; break;
        default: s = s3; d = d3; break;
    }
    for (int i = blockIdx.x*blockDim.x + threadIdx.x; i < n4; i += gridDim.x*blockDim.x) {
        float4 v = ((const float4*)s)[i];
        ((half2*)d)[2*i]   = __floats2half2_rn(v.x, v.y);
        ((half2*)d)[2*i+1] = __floats2half2_rn(v.z, v.w);
    }
}

// --------------------------- mask row-flag prepass (coalesced) ---------------
// One 256-thread block per mask row. Thread t reads ints [8t, 8t+8) —
// warp covers 1KB contiguous (fully coalesced). Tile i (64 cols) = threads
// [8i, 8i+8). ballot -> 4 tile-flags per warp (8-bit groups); thread 0
// assembles the 32-bit row word.
__global__ void rowflags(const int* __restrict__ m, unsigned* __restrict__ out)
{
    const int row = blockIdx.x, tid = threadIdx.x;
    const int4* p = (const int4*)(m + (size_t)row*SEQ) + tid*2;
    int4 a = p[0], b = p[1];
    int ok = (a.x && a.y && a.z && a.w && b.x && b.y && b.z && b.w) ? 1 : 0;
    unsigned bits = __ballot_sync(0xffffffffu, ok);
    __shared__ unsigned wb[8];
    if ((tid & 31) == 0) wb[tid >> 5] = bits;
    __syncthreads();
    if (tid == 0) {
        unsigned f = 0;
#pragma unroll
        for (int w = 0; w < 8; w++) {
            unsigned x = wb[w];
#pragma unroll
            for (int t2 = 0; t2 < 4; t2++)
                if (((x >> (t2*8)) & 0xFFu) == 0xFFu) f |= 1u << (w*4 + t2);
        }
        out[row] = f;
    }
}

// ---------------------------------------------------------------------------
// C = scale * A @ W^T (+bias). z = blockIdx.z selects (A, W, C, scale).
// CTA 128x128, 256 threads / 8 warps (2m x 4n), warp tile 64x32, Kt=32,
// 3-stage cp.async pipeline, ldmatrix.x4 fragment loads.
// ---------------------------------------------------------------------------
struct GemmArgs {
    const __half* A[3]; const __half* W[3]; void* C[3];
    float scale[3]; const float* bias; int split;
};

#define GLD 40   // smem row stride in halves (80B, conflict-free)
__global__ __launch_bounds__(256, 2) void gemm_h(GemmArgs ga)
{
    extern __shared__ __half sm[];
    __half* smA = sm;                 // 3 x [128][GLD]
    __half* smB = sm + 3*128*GLD;     // 3 x [128][GLD]

    const int tid = threadIdx.x, lane = tid & 31;
    const int g = lane >> 2, t = lane & 3, wid = tid >> 5;
    const int wm = (wid & 1) * 64, wn = (wid >> 1) * 32;
    const int m0 = blockIdx.y * 128, n0 = blockIdx.x * 128;
    const int z = blockIdx.z;

    const __half* Ag = ga.A[z] + (size_t)m0 * DMODEL;
    const __half* Wg = ga.W[z] + (size_t)n0 * DMODEL;
    const float scale = ga.scale[z];

    int crow[2], coff[2];
#pragma unroll
    for (int l = 0; l < 2; l++) {
        int c = tid + l*256;
        crow[l] = c >> 2; coff[l] = (c & 3) * 8;
    }

    auto issue = [&](int tile) {
        int buf = tile % 3, k0 = tile * 32;
        unsigned da = smem_u32(smA + buf*128*GLD);
        unsigned db = smem_u32(smB + buf*128*GLD);
#pragma unroll
        for (int l = 0; l < 2; l++) {
            cpa16(da + (crow[l]*GLD + coff[l])*2, Ag + (size_t)crow[l]*DMODEL + k0 + coff[l]);
            cpa16(db + (crow[l]*GLD + coff[l])*2, Wg + (size_t)crow[l]*DMODEL + k0 + coff[l]);
        }
    };
    issue(0); cpa_commit();
    issue(1); cpa_commit();

    // ldmatrix per-thread address constants
    const int arow_c = lane & 15;              // A: row within 16-row frag
    const int akh    = (lane >> 4) * 8;        // A: k-half select
    const int brow_c = ((lane >> 4) & 1) * 8 + (lane & 7);  // B: row within fn-pair
    const int bkh    = ((lane >> 3) & 1) * 8;               // B: k-half select

    float acc[4][4][4] = {};

    for (int i = 0; i < 32; i++) {
        cpa_wait1();
        __syncthreads();
        if (i + 2 < 32) issue(i + 2);
        cpa_commit();

        const unsigned abase = smem_u32(smA + (i % 3)*128*GLD);
        const unsigned bbase = smem_u32(smB + (i % 3)*128*GLD);
#pragma unroll
        for (int ks = 0; ks < 2; ks++) {
            const int k = ks * 16;
            unsigned af[4][4], bf[4][2];
#pragma unroll
            for (int fm = 0; fm < 4; fm++)
                ldmx4(af[fm][0], af[fm][1], af[fm][2], af[fm][3],
                      abase + ((wm + fm*16 + arow_c)*GLD + k + akh)*2);
#pragma unroll
            for (int p = 0; p < 2; p++) {
                unsigned r0, r1, r2, r3;
                ldmx4(r0, r1, r2, r3,
                      bbase + ((wn + p*16 + brow_c)*GLD + k + bkh)*2);
                bf[2*p][0]   = r0; bf[2*p][1]   = r1;
                bf[2*p+1][0] = r2; bf[2*p+1][1] = r3;
            }
#pragma unroll
            for (int fm = 0; fm < 4; fm++)
#pragma unroll
                for (int fn = 0; fn < 4; fn++) mma16(acc[fm][fn], af[fm], bf[fn]);
        }
        __syncthreads();
    }

#pragma unroll
    for (int fn = 0; fn < 4; fn++) {
        int n = n0 + wn + fn*8 + 2*t;
        float b0 = 0.f, b1 = 0.f;
        if (ga.bias) { b0 = ga.bias[n]; b1 = ga.bias[n+1]; }
#pragma unroll
        for (int fm = 0; fm < 4; fm++) {
#pragma unroll
            for (int rr = 0; rr < 2; rr++) {
                int m = m0 + wm + fm*16 + g + rr*8;
                float vx = acc[fm][fn][rr*2]   * scale + b0;
                float vy = acc[fm][fn][rr*2+1] * scale + b1;
                if (ga.split) {
                    int bb = m >> 11, ss = m & (SEQ-1);
                    int hh = n >> 6,  dd = n & 63;
                    __half* C = (__half*)ga.C[z];
                    *(half2*)(C + (size_t)(((bb*HEADS + hh)*SEQ) + ss)*DKH + dd) =
                        __floats2half2_rn(vx, vy);
                } else {
                    float* C = (float*)ga.C[z];
                    *(float2*)(C + (size_t)m*DMODEL + n) = make_float2(vx, vy);
                }
            }
        }
    }
}

// ---------------------------------------------------------------------------
// Flash attention fp16 (round-12 structure, 255 regs / 2 CTAs per SM).
// Br=128 (4 warps x 32 q-rows), Bc=64, 2-stage cp.async K/V pipeline,
// exp2-domain softmax, P packed lazily in PV loop. Mask via per-row tile
// bitmask: one word per stat-row loaded once; detailed int2 loads only on
// tiles with zeros (slow path, normally never taken).
// ---------------------------------------------------------------------------
#define FLD 72   // smem row stride in halves (144B)
#define FTS (64*FLD)
__global__ __launch_bounds__(128, 2) void flash_h(
    const __half* __restrict__ Qp, const __half* __restrict__ Kp,
    const __half* __restrict__ Vp, const int* __restrict__ mask,
    const unsigned* __restrict__ rf, __half* __restrict__ Out)
{
    extern __shared__ __half fsm[];
    __half* Qs = fsm;                 // [128][FLD]
    __half* Ks = fsm + 2*FTS;         // 2 x [64][FLD]
    __half* Vs = fsm + 4*FTS;         // 2 x [64][FLD]

    const int tid = threadIdx.x, lane = tid & 31;
    const int g = lane >> 2, t = lane & 3, wid = tid >> 5;
    const int q0 = blockIdx.x * 128, h = blockIdx.y, b = blockIdx.z;
    const int qw = wid * 32;

    const __half* Qg = Qp + (size_t)((b*HEADS + h)*SEQ + q0)*DKH;
    const __half* Kg = Kp + (size_t)((b*HEADS + h)*SEQ)*DKH;
    const __half* Vg = Vp + (size_t)((b*HEADS + h)*SEQ)*DKH;

    // K/V tile: 64 rows x 8 chunks(16B) = 512 chunks; 4/thread
    int crow[4], coff[4];
#pragma unroll
    for (int l = 0; l < 4; l++) {
        int c = tid + l*128;
        crow[l] = c >> 3; coff[l] = (c & 7) * 8;
    }

    auto issue_kv = [&](int tile) {
        int buf = tile & 1, k0 = tile * 64;
        unsigned dk = smem_u32(Ks + buf*FTS);
        unsigned dv = smem_u32(Vs + buf*FTS);
#pragma unroll
        for (int l = 0; l < 4; l++) {
            cpa16(dk + (crow[l]*FLD + coff[l])*2, Kg + (size_t)(k0 + crow[l])*DKH + coff[l]);
            cpa16(dv + (crow[l]*FLD + coff[l])*2, Vg + (size_t)(k0 + crow[l])*DKH + coff[l]);
        }
    };
    {   // group 0: Q (128 rows = 1024 chunks, 8/thread) + K/V tile 0
        unsigned dq = smem_u32(Qs);
#pragma unroll
        for (int l = 0; l < 8; l++) {
            int c = tid + l*128;
            int r = c >> 3, cc = (c & 7) * 8;
            cpa16(dq + (r*FLD + cc)*2, Qg + (size_t)r*DKH + cc);
        }
        issue_kv(0); cpa_commit();
    }

    // ldmatrix per-thread address constants
    const int krow_c = ((lane >> 4) & 1) * 8 + (lane & 7);  // K, non-trans
    const int kkh    = ((lane >> 3) & 1) * 8;
    const int vrow_c = (lane & 7) + ((lane >> 3) & 1) * 8;  // V, trans
    const int vcol_c = (lane >> 4) * 8;

    // mask base + per-stat-row tile bitmasks (one word per row, loaded once)
    const int* mbase = mask + (size_t)(b*SEQ + q0 + qw + g)*SEQ + 2*t;
    unsigned rmb[2][2];
#pragma unroll
    for (int rb = 0; rb < 2; rb++)
#pragma unroll
        for (int rr = 0; rr < 2; rr++)
            rmb[rb][rr] = rf[b*SEQ + q0 + qw + rb*16 + rr*8 + g];

    unsigned aq[2][4][4];
    float o[2][8][4] = {};
    float m_[2][2] = {{-1e30f,-1e30f},{-1e30f,-1e30f}};
    float l_[2][2] = {{0.f,0.f},{0.f,0.f}};

    for (int i = 0; i < 32; i++) {
        cpa_wait0();
        __syncthreads();                 // tile i ready; all reads of other buf done
        if (i + 1 < 32) { issue_kv(i + 1); cpa_commit(); }

        if (i == 0) {   // Q frags -> registers (once)
#pragma unroll
            for (int rb = 0; rb < 2; rb++)
#pragma unroll
                for (int ks = 0; ks < 4; ks++) {
                    const int r = qw + rb*16 + g, k = ks*16;
                    aq[rb][ks][0] = *(const unsigned*)&Qs[r*FLD + k + 2*t];
                    aq[rb][ks][1] = *(const unsigned*)&Qs[(r+8)*FLD + k + 2*t];
                    aq[rb][ks][2] = *(const unsigned*)&Qs[r*FLD + k + 8 + 2*t];
                    aq[rb][ks][3] = *(const unsigned*)&Qs[(r+8)*FLD + k + 8 + 2*t];
                }
        }

        const unsigned kbase = smem_u32(Ks + (i & 1)*FTS);
        const unsigned vbase = smem_u32(Vs + (i & 1)*FTS);

        // S = Q K^T; each ldmatrix.x4 feeds 4 MMAs (2 row-frags x 2 cols)
        float sc[2][8][4] = {};
#pragma unroll
        for (int ks = 0; ks < 4; ks++) {
            const int k = ks*16;
#pragma unroll
            for (int p = 0; p < 4; p++) {
                unsigned r0, r1, r2, r3;
                unsigned addr = kbase + ((p*16 + krow_c)*FLD + k + kkh)*2;
                ldmx4(r0, r1, r2, r3, addr);
                unsigned b0[2] = {r0, r1}, b1[2] = {r2, r3};
#pragma unroll
                for (int rb = 0; rb < 2; rb++) {
                    mma16(sc[rb][2*p],   aq[rb][ks], b0);
                    mma16(sc[rb][2*p+1], aq[rb][ks], b1);
                }
            }
        }

        // mask: bit test per stat-row; detailed loads only if tile has zeros
#pragma unroll
        for (int rb = 0; rb < 2; rb++)
#pragma unroll
            for (int rr = 0; rr < 2; rr++) {
                if (!((rmb[rb][rr] >> i) & 1u)) {
                    const int* mr = mbase + (size_t)(rb*16 + rr*8)*SEQ + i*64;
#pragma unroll
                    for (int fn = 0; fn < 8; fn++) {
                        int2 mv = *(const int2*)(mr + fn*8);
                        if (mv.x == 0) sc[rb][fn][rr*2]   = -1e30f;
                        if (mv.y == 0) sc[rb][fn][rr*2+1] = -1e30f;
                    }
                }
            }

        // online softmax (exp2 domain)
#pragma unroll
        for (int rb = 0; rb < 2; rb++)
#pragma unroll
            for (int rr = 0; rr < 2; rr++) {
                float rmax = -1e30f;
#pragma unroll
                for (int fn = 0; fn < 8; fn++)
                    rmax = fmaxf(rmax, fmaxf(sc[rb][fn][rr*2], sc[rb][fn][rr*2+1]));
                rmax = fmaxf(rmax, __shfl_xor_sync(0xffffffffu, rmax, 1));
                rmax = fmaxf(rmax, __shfl_xor_sync(0xffffffffu, rmax, 2));
                float mn = fmaxf(m_[rb][rr], rmax);
                float alpha = exp2f(m_[rb][rr] - mn);
                float rsum = 0.f;
#pragma unroll
                for (int fn = 0; fn < 8; fn++) {
                    sc[rb][fn][rr*2]   = exp2f(sc[rb][fn][rr*2]   - mn);
                    sc[rb][fn][rr*2+1] = exp2f(sc[rb][fn][rr*2+1] - mn);
                    rsum += sc[rb][fn][rr*2] + sc[rb][fn][rr*2+1];
                }
                rsum += __shfl_xor_sync(0xffffffffu, rsum, 1);
                rsum += __shfl_xor_sync(0xffffffffu, rsum, 2);
                l_[rb][rr] = l_[rb][rr]*alpha + rsum;
                m_[rb][rr] = mn;
#pragma unroll
                for (int fn = 0; fn < 8; fn++) {
                    o[rb][fn][rr*2]   *= alpha;
                    o[rb][fn][rr*2+1] *= alpha;
                }
            }

        // O += P @ V; P packed lazily per ks (round-12 structure)
#pragma unroll
        for (int ks = 0; ks < 4; ks++) {
            const int k = ks*16;
            unsigned ap[2][4];
#pragma unroll
            for (int rb = 0; rb < 2; rb++) {
                ap[rb][0] = packh2(sc[rb][2*ks][0],   sc[rb][2*ks][1]);
                ap[rb][1] = packh2(sc[rb][2*ks][2],   sc[rb][2*ks][3]);
                ap[rb][2] = packh2(sc[rb][2*ks+1][0], sc[rb][2*ks+1][1]);
                ap[rb][3] = packh2(sc[rb][2*ks+1][2], sc[rb][2*ks+1][3]);
            }
#pragma unroll
            for (int fp = 0; fp < 4; fp++) {
                unsigned r0, r1, r2, r3;
                unsigned addr = vbase + ((k + vrow_c)*FLD + fp*16 + vcol_c)*2;
                ldmx4t(r0, r1, r2, r3, addr);
                unsigned b0[2] = {r0, r1}, b1[2] = {r2, r3};
#pragma unroll
                for (int rb = 0; rb < 2; rb++) {
                    mma16(o[rb][2*fp],   ap[rb], b0);
                    mma16(o[rb][2*fp+1], ap[rb], b1);
                }
            }
        }
    }

    // normalize + half store, merged [B,S, h*64+d]
#pragma unroll
    for (int rb = 0; rb < 2; rb++)
#pragma unroll
        for (int rr = 0; rr < 2; rr++) {
            float inv = 1.0f / l_[rb][rr];
            int row = q0 + qw + rb*16 + rr*8 + g;
            __half* op = Out + (size_t)(b*SEQ + row)*DMODEL + h*DKH + 2*t;
#pragma unroll
            for (int fn = 0; fn < 8; fn++)
                *(half2*)(op + fn*8) =
                    __floats2half2_rn(o[rb][fn][rr*2]*inv, o[rb][fn][rr*2+1]*inv);
        }
}

// ---------------------------------------------------------------------------
extern "C" void kernel_launch(void* const* d_in, const int* in_sizes, int n_in,
                              void* d_out, int out_size)
{
    const float* q  = (const float*)d_in[0];
    const float* k  = (const float*)d_in[1];
    const float* v  = (const float*)d_in[2];
    const int*   mk = (const int*)  d_in[3];
    const float* wq = (const float*)d_in[4];
    const float* wk = (const float*)d_in[5];
    const float* wv = (const float*)d_in[6];
    const float* wo = (const float*)d_in[7];
    const float* bo = (const float*)d_in[8];
    float* out = (float*)d_out;

    __half *qh, *kh, *vh, *wqh, *wkh, *wvh, *woh, *qp, *kp, *vp, *ao;
    unsigned* rfp;
    cudaGetSymbolAddress((void**)&qh,  g_qh);
    cudaGetSymbolAddress((void**)&kh,  g_kh);
    cudaGetSymbolAddress((void**)&vh,  g_vh);
    cudaGetSymbolAddress((void**)&wqh, g_wqh);
    cudaGetSymbolAddress((void**)&wkh, g_wkh);
    cudaGetSymbolAddress((void**)&wvh, g_wvh);
    cudaGetSymbolAddress((void**)&woh, g_woh);
    cudaGetSymbolAddress((void**)&qp,  g_qp);
    cudaGetSymbolAddress((void**)&kp,  g_kp);
    cudaGetSymbolAddress((void**)&vp,  g_vp);
    cudaGetSymbolAddress((void**)&ao,  g_ao);
    cudaGetSymbolAddress((void**)&rfp, g_rf);

    const int gemm_smem  = 6 * 128 * GLD * 2;      // 61440 B
    const int flash_smem = 6 * FTS * 2;            // 55296 B
    cudaFuncSetAttribute(gemm_h,  cudaFuncAttributeMaxDynamicSharedMemorySize, gemm_smem);
    cudaFuncSetAttribute(flash_h, cudaFuncAttributeMaxDynamicSharedMemorySize, flash_smem);

    // fp32 -> fp16 conversions + coalesced mask row-flag prepass
    f2h4<<<dim3(512, 3), 256>>>(q, k, v, nullptr, qh, kh, vh, nullptr, MR*DMODEL/4);
    f2h4<<<dim3(128, 4), 256>>>(wq, wk, wv, wo, wqh, wkh, wvh, woh, DMODEL*DMODEL/4);
    rowflags<<<MR, 256>>>(mk, rfp);   // one block per row, coalesced

    // fused QKV projections; q scale = log2(e)/sqrt(64) for exp2-domain softmax
    GemmArgs pa;
    pa.A[0] = qh;  pa.A[1] = kh;  pa.A[2] = vh;
    pa.W[0] = wqh; pa.W[1] = wkh; pa.W[2] = wvh;
    pa.C[0] = qp;  pa.C[1] = kp;  pa.C[2] = vp;
    pa.scale[0] = 0.125f * 1.44269504088896f; pa.scale[1] = 1.0f; pa.scale[2] = 1.0f;
    pa.bias = nullptr; pa.split = 1;
    gemm_h<<<dim3(DMODEL/128, MR/128, 3), 256, gemm_smem>>>(pa);

    flash_h<<<dim3(SEQ/128, HEADS, BATCH), 128, flash_smem>>>(qp, kp, vp, mk, rfp, ao);

    // output projection + bias
    GemmArgs oa;
    oa.A[0] = ao; oa.A[1] = nullptr; oa.A[2] = nullptr;
    oa.W[0] = woh; oa.W[1] = nullptr; oa.W[2] = nullptr;
    oa.C[0] = out; oa.C[1] = nullptr; oa.C[2] = nullptr;
    oa.scale[0] = 1.0f; oa.scale[1] = 1.0f; oa.scale[2] = 1.0f;
    oa.bias = bo; oa.split = 0;
    gemm_h<<<dim3(DMODEL/128, MR/128, 1), 256, gemm_smem>>>(oa);
}